// round 5
// baseline (speedup 1.0000x reference)
#include <cuda_runtime.h>
#include <cuda_bf16.h>
#include <cstdint>

// WeightAndSum: out[seg[r], :] += feats[r, :] * sigmoid(dot(feats[r,:], w) + b)
// N = 2,000,000 rows, D = 128, B = 65536 segments, segment_ids sorted ascending.
//
// Per-warp cp.async (LDGSTS) pipeline: each warp owns a private DEPTH-stage
// SMEM ring; stage = 4 rows (2KB) + 16B of segment ids, filled by
// cp.async.cg 16B/lane (coalesced linear 2KB copies — rows are contiguous),
// synced with per-warp commit_group/wait_group. No block barriers. In-flight
// bytes live in SMEM, not registers, so latency hiding is decoupled from
// occupancy. Consumer does conflict-free LDS.128, 4 parallel warp butterflies,
// sigmoid gates, register-accumulated segment sums. Interior segments flushed
// with plain float4 stores (exclusive by sortedness, out pre-zeroed);
// boundary segments flushed with atomicAdd.

#define D_DIM 128
#define ROWS_PER_WARP 256
#define THREADS 256
#define WARPS (THREADS / 32)
#define DEPTH 4
#define GROUP_ROWS 4
#define STAGE_DATA (GROUP_ROWS * D_DIM * 4)   // 2048 B
#define STAGE_BYTES (STAGE_DATA + 16)          // + seg int4
#define SMEM_BYTES (WARPS * DEPTH * STAGE_BYTES)

__device__ __forceinline__ void cp16(uint32_t dst_smem, const void* src) {
    asm volatile("cp.async.cg.shared.global [%0], [%1], 16;\n"
                 :: "r"(dst_smem), "l"(src));
}

__global__ __launch_bounds__(THREADS, 3) void was_kernel(
    const float* __restrict__ feats,
    const int*   __restrict__ seg,
    const float* __restrict__ w,
    const float* __restrict__ b,
    float*       __restrict__ out,
    int N)
{
    extern __shared__ char smem_raw[];

    const int wid   = threadIdx.x >> 5;
    const int lane  = threadIdx.x & 31;
    const int gwarp = blockIdx.x * WARPS + wid;

    long start = (long)gwarp * ROWS_PER_WARP;
    if (start >= N) return;
    long end = start + ROWS_PER_WARP;
    if (end > N) end = N;

    char* wsm = smem_raw + (size_t)wid * DEPTH * STAGE_BYTES;
    const uint32_t wsm_s = (uint32_t)__cvta_generic_to_shared(wsm);

    const float4 wv  = reinterpret_cast<const float4*>(w)[lane];
    const float bias = __ldg(b);

    float4 acc = make_float4(0.f, 0.f, 0.f, 0.f);
    int  cur = __ldg(&seg[start]);
    bool started_inside = false;

#define PROC_ROW(S, F, G)                                                   \
    do {                                                                    \
        if ((S) != cur) {                                                   \
            float* o = out + (size_t)cur * D_DIM + lane * 4;                \
            if (started_inside) {                                           \
                *reinterpret_cast<float4*>(o) = acc;                        \
            } else {                                                        \
                atomicAdd(o + 0, acc.x);                                    \
                atomicAdd(o + 1, acc.y);                                    \
                atomicAdd(o + 2, acc.z);                                    \
                atomicAdd(o + 3, acc.w);                                    \
            }                                                               \
            acc = make_float4(0.f, 0.f, 0.f, 0.f);                         \
            cur = (S);                                                      \
            started_inside = true;                                          \
        }                                                                   \
        acc.x += (F).x * (G);                                               \
        acc.y += (F).y * (G);                                               \
        acc.z += (F).z * (G);                                               \
        acc.w += (F).w * (G);                                               \
    } while (0)

    const int G = (int)((end - start) >> 2);  // full 4-row groups

    // ---- issue helper (macro: g must be in range) ----
#define ISSUE(gidx)                                                          \
    do {                                                                     \
        const long gr = start + (long)(gidx) * GROUP_ROWS;                   \
        const char* gsrc = reinterpret_cast<const char*>(feats) + gr * 512;  \
        const uint32_t dst = wsm_s + ((gidx) & (DEPTH - 1)) * STAGE_BYTES;   \
        cp16(dst + 0 * 512 + lane * 16, gsrc + 0 * 512 + lane * 16);         \
        cp16(dst + 1 * 512 + lane * 16, gsrc + 1 * 512 + lane * 16);         \
        cp16(dst + 2 * 512 + lane * 16, gsrc + 2 * 512 + lane * 16);         \
        cp16(dst + 3 * 512 + lane * 16, gsrc + 3 * 512 + lane * 16);         \
        if (lane == 0) cp16(dst + STAGE_DATA, seg + gr);                     \
    } while (0)

    // ---- prologue: prime DEPTH-1 stages ----
#pragma unroll
    for (int s = 0; s < DEPTH - 1; ++s) {
        if (s < G) ISSUE(s);
        asm volatile("cp.async.commit_group;\n");
    }

    // ---- steady loop ----
    for (int g = 0; g < G; ++g) {
        const int gi = g + DEPTH - 1;
        if (gi < G) ISSUE(gi);
        asm volatile("cp.async.commit_group;\n");
        asm volatile("cp.async.wait_group %0;\n" :: "n"(DEPTH - 1));
        __syncwarp();

        const char* sbase = wsm + (g & (DEPTH - 1)) * STAGE_BYTES;
        const int4 s4 = *reinterpret_cast<const int4*>(sbase + STAGE_DATA);
        const float4 f0 = *reinterpret_cast<const float4*>(sbase + 0 * 512 + lane * 16);
        const float4 f1 = *reinterpret_cast<const float4*>(sbase + 1 * 512 + lane * 16);
        const float4 f2 = *reinterpret_cast<const float4*>(sbase + 2 * 512 + lane * 16);
        const float4 f3 = *reinterpret_cast<const float4*>(sbase + 3 * 512 + lane * 16);

        float p0 = f0.x * wv.x + f0.y * wv.y + f0.z * wv.z + f0.w * wv.w;
        float p1 = f1.x * wv.x + f1.y * wv.y + f1.z * wv.z + f1.w * wv.w;
        float p2 = f2.x * wv.x + f2.y * wv.y + f2.z * wv.z + f2.w * wv.w;
        float p3 = f3.x * wv.x + f3.y * wv.y + f3.z * wv.z + f3.w * wv.w;

#pragma unroll
        for (int o = 16; o > 0; o >>= 1) {
            p0 += __shfl_xor_sync(0xffffffffu, p0, o);
            p1 += __shfl_xor_sync(0xffffffffu, p1, o);
            p2 += __shfl_xor_sync(0xffffffffu, p2, o);
            p3 += __shfl_xor_sync(0xffffffffu, p3, o);
        }

        const float g0 = 1.0f / (1.0f + __expf(-(p0 + bias)));
        const float g1 = 1.0f / (1.0f + __expf(-(p1 + bias)));
        const float g2 = 1.0f / (1.0f + __expf(-(p2 + bias)));
        const float g3 = 1.0f / (1.0f + __expf(-(p3 + bias)));

        PROC_ROW(s4.x, f0, g0);
        PROC_ROW(s4.y, f1, g1);
        PROC_ROW(s4.z, f2, g2);
        PROC_ROW(s4.w, f3, g3);
    }
#undef ISSUE

    // ---- tail rows (chunk not multiple of 4; unused for N = 2M) ----
    for (long r = start + (long)G * GROUP_ROWS; r < end; ++r) {
        const int s = __ldg(&seg[r]);
        const float4 f =
            reinterpret_cast<const float4*>(feats + (size_t)r * D_DIM)[lane];
        float p = f.x * wv.x + f.y * wv.y + f.z * wv.z + f.w * wv.w;
#pragma unroll
        for (int o = 16; o > 0; o >>= 1) p += __shfl_xor_sync(0xffffffffu, p, o);
        const float gg = 1.0f / (1.0f + __expf(-(p + bias)));
        PROC_ROW(s, f, gg);
    }
#undef PROC_ROW

    // final segment may continue into the next warp's chunk -> atomic
    float* o = out + (size_t)cur * D_DIM + lane * 4;
    atomicAdd(o + 0, acc.x);
    atomicAdd(o + 1, acc.y);
    atomicAdd(o + 2, acc.z);
    atomicAdd(o + 3, acc.w);
}

extern "C" void kernel_launch(void* const* d_in, const int* in_sizes, int n_in,
                              void* d_out, int out_size)
{
    const float* feats = (const float*)d_in[0];
    const int*   seg   = (const int*)d_in[1];
    const float* w     = (const float*)d_in[2];
    const float* b     = (const float*)d_in[3];
    float*       out   = (float*)d_out;

    const int N = in_sizes[1];  // element count of segment_ids == N rows

    cudaFuncSetAttribute(was_kernel,
                         cudaFuncAttributeMaxDynamicSharedMemorySize,
                         SMEM_BYTES);

    cudaMemsetAsync(d_out, 0, (size_t)out_size * sizeof(float), 0);

    const int warps  = (N + ROWS_PER_WARP - 1) / ROWS_PER_WARP;
    const int blocks = (warps + WARPS - 1) / WARPS;
    was_kernel<<<blocks, THREADS, SMEM_BYTES>>>(feats, seg, w, b, out, N);
}

// round 6
// speedup vs baseline: 1.1055x; 1.1055x over previous
#include <cuda_runtime.h>
#include <cuda_bf16.h>

// WeightAndSum: out[seg[r], :] = sum_{r in segment} feats[r,:] * sigmoid(dot(feats[r,:], w) + b)
// N = 2,000,000 rows, D = 128, B = 65536 segments, segment_ids sorted ascending.
//
// Two-kernel plan, zero atomics, zero memset:
//  1) offs_kernel: build g_offs[b] = first row index of segment b (g_offs[B]=N),
//     handling empty segments, from the sorted segment_ids array.
//  2) was_kernel: warp per segment. Each warp exclusively owns its segment's
//     contiguous row range: stream rows (4-row groups, register
//     double-buffered), gate, accumulate in registers, then ONE plain float4
//     store per lane. Every output element is written exactly once (empty
//     segments store zeros), so the poisoned output needs no memset and there
//     are no atomics anywhere. Inner loop is branchless.

#define D_DIM 128
#define THREADS 256
#define WARPS (THREADS / 32)
#define MAX_B 65536

__device__ int g_offs[MAX_B + 1];

__global__ __launch_bounds__(256) void offs_kernel(
    const int* __restrict__ seg, int N, int B)
{
    const int i = blockIdx.x * blockDim.x + threadIdx.x;
    if (i >= N) return;
    const int s    = seg[i];
    const int prev = (i == 0) ? -1 : seg[i - 1];
    // i is the first row of segments (prev, s] (empties get start = i, and
    // their end g_offs[b+1] will also be i -> length 0)
    for (int bb = prev + 1; bb <= s; ++bb) g_offs[bb] = i;
    if (i == N - 1) {
        for (int bb = s + 1; bb <= B; ++bb) g_offs[bb] = N;
    }
}

__global__ __launch_bounds__(THREADS) void was_kernel(
    const float* __restrict__ feats,
    const float* __restrict__ w,
    const float* __restrict__ b,
    float*       __restrict__ out,
    int B)
{
    const int wid  = threadIdx.x >> 5;
    const int lane = threadIdx.x & 31;
    const int s    = blockIdx.x * WARPS + wid;
    if (s >= B) return;

    const int start = g_offs[s];
    const int end   = g_offs[s + 1];

    const float4 wv  = reinterpret_cast<const float4*>(w)[lane];
    const float bias = __ldg(b);

    float4 acc = make_float4(0.f, 0.f, 0.f, 0.f);

    int r = start;
    const int stop = start + ((end - start) & ~3);  // full 4-row groups

    if (r < stop) {
        // ---- prologue: load group 0 ----
        const float4* base =
            reinterpret_cast<const float4*>(feats) + (size_t)r * (D_DIM / 4) + lane;
        float4 f0 = __ldcs(base);
        float4 f1 = __ldcs(base + (D_DIM / 4));
        float4 f2 = __ldcs(base + 2 * (D_DIM / 4));
        float4 f3 = __ldcs(base + 3 * (D_DIM / 4));

        for (;;) {
            const int rn   = r + 4;
            const bool more = (rn < stop);

            // ---- prefetch next group before current chain ----
            float4 f0n, f1n, f2n, f3n;
            if (more) {
                const float4* bn =
                    reinterpret_cast<const float4*>(feats) + (size_t)rn * (D_DIM / 4) + lane;
                f0n = __ldcs(bn);
                f1n = __ldcs(bn + (D_DIM / 4));
                f2n = __ldcs(bn + 2 * (D_DIM / 4));
                f3n = __ldcs(bn + 3 * (D_DIM / 4));
            }

            // ---- 4 per-lane partial dots, 4 parallel butterflies ----
            float p0 = f0.x * wv.x + f0.y * wv.y + f0.z * wv.z + f0.w * wv.w;
            float p1 = f1.x * wv.x + f1.y * wv.y + f1.z * wv.z + f1.w * wv.w;
            float p2 = f2.x * wv.x + f2.y * wv.y + f2.z * wv.z + f2.w * wv.w;
            float p3 = f3.x * wv.x + f3.y * wv.y + f3.z * wv.z + f3.w * wv.w;

#pragma unroll
            for (int o = 16; o > 0; o >>= 1) {
                p0 += __shfl_xor_sync(0xffffffffu, p0, o);
                p1 += __shfl_xor_sync(0xffffffffu, p1, o);
                p2 += __shfl_xor_sync(0xffffffffu, p2, o);
                p3 += __shfl_xor_sync(0xffffffffu, p3, o);
            }

            const float g0 = 1.0f / (1.0f + __expf(-(p0 + bias)));
            const float g1 = 1.0f / (1.0f + __expf(-(p1 + bias)));
            const float g2 = 1.0f / (1.0f + __expf(-(p2 + bias)));
            const float g3 = 1.0f / (1.0f + __expf(-(p3 + bias)));

            // ---- branchless accumulate (single owner: no flush logic) ----
            acc.x += f0.x * g0 + f1.x * g1 + f2.x * g2 + f3.x * g3;
            acc.y += f0.y * g0 + f1.y * g1 + f2.y * g2 + f3.y * g3;
            acc.z += f0.z * g0 + f1.z * g1 + f2.z * g2 + f3.z * g3;
            acc.w += f0.w * g0 + f1.w * g1 + f2.w * g2 + f3.w * g3;

            if (!more) { r = rn; break; }
            f0 = f0n; f1 = f1n; f2 = f2n; f3 = f3n;
            r = rn;
        }
    }

    // ---- tail rows (0..3) ----
    for (; r < end; ++r) {
        const float4 f =
            reinterpret_cast<const float4*>(feats)[(size_t)r * (D_DIM / 4) + lane];
        float p = f.x * wv.x + f.y * wv.y + f.z * wv.z + f.w * wv.w;
#pragma unroll
        for (int o = 16; o > 0; o >>= 1) p += __shfl_xor_sync(0xffffffffu, p, o);
        const float g = 1.0f / (1.0f + __expf(-(p + bias)));
        acc.x += f.x * g;
        acc.y += f.y * g;
        acc.z += f.z * g;
        acc.w += f.w * g;
    }

    // ---- exclusive owner: single plain store (zeros for empty segments) ----
    float* o = out + (size_t)s * D_DIM + lane * 4;
    *reinterpret_cast<float4*>(o) = acc;
}

extern "C" void kernel_launch(void* const* d_in, const int* in_sizes, int n_in,
                              void* d_out, int out_size)
{
    const float* feats = (const float*)d_in[0];
    const int*   seg   = (const int*)d_in[1];
    const float* w     = (const float*)d_in[2];
    const float* b     = (const float*)d_in[3];
    float*       out   = (float*)d_out;

    const int N = in_sizes[1];            // rows
    const int B = out_size / D_DIM;       // segments (65536)

    offs_kernel<<<(N + 255) / 256, 256>>>(seg, N, B);

    const int blocks = (B + WARPS - 1) / WARPS;
    was_kernel<<<blocks, THREADS>>>(feats, w, b, out, B);
}

// round 7
// speedup vs baseline: 1.1323x; 1.0243x over previous
#include <cuda_runtime.h>
#include <cuda_bf16.h>

// WeightAndSum: out[s, :] = sum_{r in segment s} feats[r,:] * sigmoid(dot(feats[r,:], w) + b)
// N = 2,000,000 rows, D = 128, B = 65536 segments, segment_ids sorted ascending.
//
// Plan (zero atomics, zero memset):
//  1) offs_kernel (vectorized): g_offs[b] = first row of segment b, g_offs[B]=N.
//  2) was_kernel: warp t exclusively owns segments [t*SPW, (t+1)*SPW). Their
//     rows are one contiguous range (sorted ids), streamed with a register
//     double-buffered 4-row pipeline. Segment boundaries detected by comparing
//     the row counter against nb = g_offs[cur+1] (no seg loads in the hot
//     loop). Flushes are plain float4 stores; empty segments get zero stores.
//     Every output element written exactly once.

#define D_DIM 128
#define THREADS 256
#define WARPS (THREADS / 32)
#define SPW 4              // segments per warp
#define MAX_B 65536

__device__ int g_offs[MAX_B + 1];

__global__ __launch_bounds__(256) void offs_kernel(
    const int* __restrict__ seg, int N, int B)
{
    const int i    = blockIdx.x * blockDim.x + threadIdx.x;
    const int base = i * 4;
    if (base >= N) return;

    const int prev = (base == 0) ? -1 : __ldg(seg + base - 1);

    int ids[4];
    if (base + 4 <= N) {
        const int4 v = *reinterpret_cast<const int4*>(seg + base);
        ids[0] = v.x; ids[1] = v.y; ids[2] = v.z; ids[3] = v.w;
    } else {
#pragma unroll
        for (int k = 0; k < 4; ++k)
            ids[k] = (base + k < N) ? __ldg(seg + base + k) : 0;
    }

    int p = prev;
#pragma unroll
    for (int k = 0; k < 4; ++k) {
        if (base + k >= N) break;
        const int s = ids[k];
        for (int bb = p + 1; bb <= s; ++bb) g_offs[bb] = base + k;
        p = s;
        if (base + k == N - 1)
            for (int bb = s + 1; bb <= B; ++bb) g_offs[bb] = N;
    }
}

__global__ __launch_bounds__(THREADS) void was_kernel(
    const float* __restrict__ feats,
    const float* __restrict__ w,
    const float* __restrict__ b,
    float*       __restrict__ out,
    int B)
{
    const int wid  = threadIdx.x >> 5;
    const int lane = threadIdx.x & 31;
    const int t    = blockIdx.x * WARPS + wid;

    const int sBeg = t * SPW;
    if (sBeg >= B) return;
    int sEnd = sBeg + SPW;
    if (sEnd > B) sEnd = B;

    const int start = g_offs[sBeg];
    const int end   = g_offs[sEnd];

    const float4 wv  = reinterpret_cast<const float4*>(w)[lane];
    const float bias = __ldg(b);

    float4 acc = make_float4(0.f, 0.f, 0.f, 0.f);
    int cur = sBeg;
    int nb  = __ldg(&g_offs[sBeg + 1]);   // first row of next segment

    // flush completed segments up to the one containing row R (rarely taken)
#define ADVANCE_TO(R)                                                       \
    while ((R) >= nb) {                                                     \
        *reinterpret_cast<float4*>(out + (size_t)cur * D_DIM + lane * 4) = acc; \
        acc = make_float4(0.f, 0.f, 0.f, 0.f);                             \
        ++cur;                                                              \
        nb = __ldg(&g_offs[cur + 1]);                                       \
    }

    int r = start;
    const int stop = start + ((end - start) & ~3);  // full 4-row groups

    if (r < stop) {
        // ---- prologue: load group 0 ----
        const float4* base =
            reinterpret_cast<const float4*>(feats) + (size_t)r * (D_DIM / 4) + lane;
        float4 f0 = __ldcs(base);
        float4 f1 = __ldcs(base + (D_DIM / 4));
        float4 f2 = __ldcs(base + 2 * (D_DIM / 4));
        float4 f3 = __ldcs(base + 3 * (D_DIM / 4));

        for (;;) {
            const int rn    = r + 4;
            const bool more = (rn < stop);

            // ---- prefetch next group before current chain/branches ----
            float4 f0n, f1n, f2n, f3n;
            if (more) {
                const float4* bn =
                    reinterpret_cast<const float4*>(feats) + (size_t)rn * (D_DIM / 4) + lane;
                f0n = __ldcs(bn);
                f1n = __ldcs(bn + (D_DIM / 4));
                f2n = __ldcs(bn + 2 * (D_DIM / 4));
                f3n = __ldcs(bn + 3 * (D_DIM / 4));
            }

            // ---- 4 per-lane partial dots, 4 parallel butterflies ----
            float p0 = f0.x * wv.x + f0.y * wv.y + f0.z * wv.z + f0.w * wv.w;
            float p1 = f1.x * wv.x + f1.y * wv.y + f1.z * wv.z + f1.w * wv.w;
            float p2 = f2.x * wv.x + f2.y * wv.y + f2.z * wv.z + f2.w * wv.w;
            float p3 = f3.x * wv.x + f3.y * wv.y + f3.z * wv.z + f3.w * wv.w;

#pragma unroll
            for (int o = 16; o > 0; o >>= 1) {
                p0 += __shfl_xor_sync(0xffffffffu, p0, o);
                p1 += __shfl_xor_sync(0xffffffffu, p1, o);
                p2 += __shfl_xor_sync(0xffffffffu, p2, o);
                p3 += __shfl_xor_sync(0xffffffffu, p3, o);
            }

            const float g0 = 1.0f / (1.0f + __expf(-(p0 + bias)));
            const float g1 = 1.0f / (1.0f + __expf(-(p1 + bias)));
            const float g2 = 1.0f / (1.0f + __expf(-(p2 + bias)));
            const float g3 = 1.0f / (1.0f + __expf(-(p3 + bias)));

            // ---- segment-boundary flushes (rare) + accumulate ----
            ADVANCE_TO(r);
            acc.x += f0.x * g0; acc.y += f0.y * g0;
            acc.z += f0.z * g0; acc.w += f0.w * g0;
            ADVANCE_TO(r + 1);
            acc.x += f1.x * g1; acc.y += f1.y * g1;
            acc.z += f1.z * g1; acc.w += f1.w * g1;
            ADVANCE_TO(r + 2);
            acc.x += f2.x * g2; acc.y += f2.y * g2;
            acc.z += f2.z * g2; acc.w += f2.w * g2;
            ADVANCE_TO(r + 3);
            acc.x += f3.x * g3; acc.y += f3.y * g3;
            acc.z += f3.z * g3; acc.w += f3.w * g3;

            if (!more) { r = rn; break; }
            f0 = f0n; f1 = f1n; f2 = f2n; f3 = f3n;
            r = rn;
        }
    }

    // ---- tail rows (0..3) ----
    for (; r < end; ++r) {
        const float4 f =
            reinterpret_cast<const float4*>(feats)[(size_t)r * (D_DIM / 4) + lane];
        float p = f.x * wv.x + f.y * wv.y + f.z * wv.z + f.w * wv.w;
#pragma unroll
        for (int o = 16; o > 0; o >>= 1) p += __shfl_xor_sync(0xffffffffu, p, o);
        const float g = 1.0f / (1.0f + __expf(-(p + bias)));
        ADVANCE_TO(r);
        acc.x += f.x * g; acc.y += f.y * g;
        acc.z += f.z * g; acc.w += f.w * g;
    }
#undef ADVANCE_TO

    // ---- final flush: current segment, then zeros for remaining empties ----
    *reinterpret_cast<float4*>(out + (size_t)cur * D_DIM + lane * 4) = acc;
    const float4 zero = make_float4(0.f, 0.f, 0.f, 0.f);
    for (int bb = cur + 1; bb < sEnd; ++bb)
        *reinterpret_cast<float4*>(out + (size_t)bb * D_DIM + lane * 4) = zero;
}

extern "C" void kernel_launch(void* const* d_in, const int* in_sizes, int n_in,
                              void* d_out, int out_size)
{
    const float* feats = (const float*)d_in[0];
    const int*   seg   = (const int*)d_in[1];
    const float* w     = (const float*)d_in[2];
    const float* b     = (const float*)d_in[3];
    float*       out   = (float*)d_out;

    const int N = in_sizes[1];            // rows
    const int B = out_size / D_DIM;       // segments (65536)

    const int groups = (N + 3) / 4;
    offs_kernel<<<(groups + 255) / 256, 256>>>(seg, N, B);

    const int warps  = (B + SPW - 1) / SPW;
    const int blocks = (warps + WARPS - 1) / WARPS;
    was_kernel<<<blocks, THREADS>>>(feats, w, b, out, B);
}